// round 8
// baseline (speedup 1.0000x reference)
#include <cuda_runtime.h>
#include <cuda_bf16.h>
#include <cstdint>

#define H 128
#define MAXN 100000
#define MAXNP (MAXN + 128)   // pad so unguarded tail-tile loads stay in bounds

// ---------------------------------------------------------------------------
// Scratch (__device__ globals; no allocation allowed)
// ---------------------------------------------------------------------------
__device__ float g_x[MAXNP * H];
__device__ float g_agg[MAXNP * H];
__device__ float g_u[MAXNP * H];
// Packed B fragments: per (mat, nrow, kc, tig) an 8-short group
// {hi(k),hi(k+1),hi(k+8),hi(k+9), lo(k),lo(k+1),lo(k+8),lo(k+9)}, k=kc*16+tig*2
// where value = W[mat][k][nrow] (transposed), hi = bf16(v), lo = bf16(v - hi).
__device__ unsigned short g_Bpack[6 * 128 * 32 * 8];

// ---------------------------------------------------------------------------
// Prep: build packed B fragment groups (one thread per 8-short group).
// ---------------------------------------------------------------------------
__global__ void prep_weights_kernel(const float* __restrict__ W1,
                                    const float* __restrict__ W2)
{
    int g = blockIdx.x * blockDim.x + threadIdx.x;
    if (g >= 6 * 128 * 32) return;
    int mat = g >> 12;            // / 4096
    int r = g & 4095;
    int nrow = r >> 5;            // / 32
    int q = r & 31;
    int kc = q >> 2;
    int tig = q & 3;
    int k = kc * 16 + tig * 2;

    const float* W = (mat < 3) ? (W1 + (size_t)mat * H * H)
                               : (W2 + (size_t)(mat - 3) * H * H);
    unsigned short s[8];
    int kk[4] = {k, k + 1, k + 8, k + 9};
    #pragma unroll
    for (int j = 0; j < 4; j++) {
        float v = W[kk[j] * H + nrow];
        __nv_bfloat16 hi = __float2bfloat16(v);
        float res = v - __bfloat162float(hi);
        __nv_bfloat16 lo = __float2bfloat16(res);
        s[j] = __bfloat16_as_ushort(hi);
        s[4 + j] = __bfloat16_as_ushort(lo);
    }
    uint4 out;
    out.x = (uint32_t)s[0] | ((uint32_t)s[1] << 16);
    out.y = (uint32_t)s[2] | ((uint32_t)s[3] << 16);
    out.z = (uint32_t)s[4] | ((uint32_t)s[5] << 16);
    out.w = (uint32_t)s[6] | ((uint32_t)s[7] << 16);
    ((uint4*)g_Bpack)[g] = out;
}

// ---------------------------------------------------------------------------
// x[i] = emb[z[i]]; also agg[i] = same (init for layer 0)
// ---------------------------------------------------------------------------
__global__ void embed_kernel(const float* __restrict__ emb,
                             const int* __restrict__ z,
                             float* __restrict__ x, float* __restrict__ agg, int N)
{
    int i = blockIdx.x * blockDim.x + threadIdx.x;
    if (i >= N * (H / 4)) return;
    int row = i >> 5;
    int c = i & 31;
    float4 v = ((const float4*)(emb + (size_t)z[row] * H))[c];
    ((float4*)x)[i] = v;
    ((float4*)agg)[i] = v;
}

// ---------------------------------------------------------------------------
// Edge messages: one warp per edge; float4 vector atomics to agg[dst].
// ---------------------------------------------------------------------------
__global__ void edge_kernel(const float* __restrict__ x,
                            float* __restrict__ agg,
                            const int* __restrict__ src,
                            const int* __restrict__ dst,
                            const float* __restrict__ ea,
                            const float* __restrict__ We,
                            const float* __restrict__ be,
                            int E)
{
    const int lane = threadIdx.x & 31;
    const int c = lane * 4;
    const int warp = (blockIdx.x * blockDim.x + threadIdx.x) >> 5;
    const int nwarps = (gridDim.x * blockDim.x) >> 5;

    const float4 w0 = *(const float4*)(We + 0 * H + c);
    const float4 w1 = *(const float4*)(We + 1 * H + c);
    const float4 w2 = *(const float4*)(We + 2 * H + c);
    const float4 w3 = *(const float4*)(We + 3 * H + c);
    const float4 bb = *(const float4*)(be + c);

    for (int e = warp; e < E; e += nwarps) {
        int s = __ldg(src + e);
        int d = __ldg(dst + e);
        float4 a = *(const float4*)(ea + 4 * (size_t)e);

        float4 p;
        p.x = bb.x + a.x * w0.x + a.y * w1.x + a.z * w2.x + a.w * w3.x;
        p.y = bb.y + a.x * w0.y + a.y * w1.y + a.z * w2.y + a.w * w3.y;
        p.z = bb.z + a.x * w0.z + a.y * w1.z + a.z * w2.z + a.w * w3.z;
        p.w = bb.w + a.x * w0.w + a.y * w1.w + a.z * w2.w + a.w * w3.w;

        float4 xv = *(const float4*)(x + (size_t)s * H + c);
        float4 m;
        m.x = fmaxf(xv.x + p.x, 0.0f);
        m.y = fmaxf(xv.y + p.y, 0.0f);
        m.z = fmaxf(xv.z + p.z, 0.0f);
        m.w = fmaxf(xv.w + p.w, 0.0f);

        atomicAdd((float4*)(agg + (size_t)d * H + c), m);
    }
}

// ---------------------------------------------------------------------------
// Tensor-core GEMM via mma.sync, split-bf16 fp32 emulation:
//   C[M,128] = act(A[M,128] @ W[128,128] + bias)
//   D = Ahi*Bhi + Ahi*Blo + Alo*Bhi, fp32 accumulate.
// CTA: 256 thr / 8 warps, 128-row tile; warp w owns rows w*16..w*16+15.
// B staged as packed 16B fragment groups (one LDS.128 per nt per kc).
// A fragments loaded directly from gmem (L2-hot) with 1-chunk prefetch.
// Smem row stride 576 B -> conflict-free LDS.128 phases; 2 CTAs/SM.
// ---------------------------------------------------------------------------
#define BROW 576                                  // bytes per n-row in smem
#define GEMM_SMEM (128 * BROW)                    // 73728 B

__device__ __forceinline__ void mma_bf16(float* c, const uint32_t* a,
                                         uint32_t b0, uint32_t b1)
{
    asm volatile(
        "mma.sync.aligned.m16n8k16.row.col.f32.bf16.bf16.f32 "
        "{%0,%1,%2,%3}, {%4,%5,%6,%7}, {%8,%9}, {%0,%1,%2,%3};"
        : "+f"(c[0]), "+f"(c[1]), "+f"(c[2]), "+f"(c[3])
        : "r"(a[0]), "r"(a[1]), "r"(a[2]), "r"(a[3]), "r"(b0), "r"(b1));
}

__global__ __launch_bounds__(256, 2) void gemm_tc_kernel(
    const float* __restrict__ A, int mat,
    const float* __restrict__ bias,
    float* __restrict__ C1, float* __restrict__ C2,
    int M, int do_silu)
{
    extern __shared__ char smraw[];

    const int tid = threadIdx.x;
    const int wid = tid >> 5;
    const int lane = tid & 31;
    const int gid = lane >> 2;       // fragment row within 8-group
    const int tig = lane & 3;        // thread-in-group (k pairs)
    const int row0 = blockIdx.x * 128;
    const int rbase = wid * 16;

    // ---- Stage packed B: 4096 uint4 (64 KB), pad each 512B row to 576B ----
    {
        const uint4* gp = (const uint4*)g_Bpack + (size_t)mat * 4096;
        #pragma unroll
        for (int it = 0; it < 16; it++) {
            int i = tid + it * 256;          // [0, 4096)
            int row = i >> 5;                // n-row
            int g = i & 31;                  // kc*4 + tig
            *(uint4*)(smraw + row * BROW + g * 16) = gp[i];
        }
    }

    // A fragment gmem pointers (rows rbase+gid and rbase+gid+8; pad rows make
    // unguarded loads safe for the final partial tile).
    const float2* A0 = (const float2*)(A + (size_t)(row0 + rbase + gid) * H) + tig;
    const float2* A1 = A0 + 8 * (H / 2);

    float acc[16][4];
    #pragma unroll
    for (int nt = 0; nt < 16; nt++)
        acc[nt][0] = acc[nt][1] = acc[nt][2] = acc[nt][3] = 0.0f;

    // Prefetch k-chunk 0
    float2 p0 = A0[0], p1 = A1[0], p2 = A0[4], p3 = A1[4];

    __syncthreads();   // B ready

    #pragma unroll
    for (int kc = 0; kc < 8; kc++) {
        float2 f0 = p0, f1 = p1, f2 = p2, f3 = p3;
        if (kc < 7) {
            p0 = A0[(kc + 1) * 8];
            p1 = A1[(kc + 1) * 8];
            p2 = A0[(kc + 1) * 8 + 4];
            p3 = A1[(kc + 1) * 8 + 4];
        }

        uint32_t ahi[4], alo[4];
        {
            __nv_bfloat162 h0 = __floats2bfloat162_rn(f0.x, f0.y);
            __nv_bfloat162 h1 = __floats2bfloat162_rn(f1.x, f1.y);
            __nv_bfloat162 h2 = __floats2bfloat162_rn(f2.x, f2.y);
            __nv_bfloat162 h3 = __floats2bfloat162_rn(f3.x, f3.y);
            __nv_bfloat162 l0 = __floats2bfloat162_rn(f0.x - __low2float(h0), f0.y - __high2float(h0));
            __nv_bfloat162 l1 = __floats2bfloat162_rn(f1.x - __low2float(h1), f1.y - __high2float(h1));
            __nv_bfloat162 l2 = __floats2bfloat162_rn(f2.x - __low2float(h2), f2.y - __high2float(h2));
            __nv_bfloat162 l3 = __floats2bfloat162_rn(f3.x - __low2float(h3), f3.y - __high2float(h3));
            ahi[0] = *(uint32_t*)&h0; ahi[1] = *(uint32_t*)&h1;
            ahi[2] = *(uint32_t*)&h2; ahi[3] = *(uint32_t*)&h3;
            alo[0] = *(uint32_t*)&l0; alo[1] = *(uint32_t*)&l1;
            alo[2] = *(uint32_t*)&l2; alo[3] = *(uint32_t*)&l3;
        }

        const int koff = (kc * 4 + tig) * 16;
        #pragma unroll
        for (int nt = 0; nt < 16; nt++) {
            const int nrow = nt * 8 + gid;
            uint4 b = *(const uint4*)(smraw + nrow * BROW + koff);
            mma_bf16(acc[nt], ahi, b.x, b.y);   // Ahi * Bhi
            mma_bf16(acc[nt], ahi, b.z, b.w);   // Ahi * Blo
            mma_bf16(acc[nt], alo, b.x, b.y);   // Alo * Bhi
        }
    }

    // ---- Epilogue: bias + (silu) + store (dual write optional) ----
    const int rowA = row0 + rbase + gid;
    const int rowB = rowA + 8;
    #pragma unroll
    for (int nt = 0; nt < 16; nt++) {
        const int col = nt * 8 + tig * 2;
        float2 bv = __ldg((const float2*)(bias + col));
        float2 va, vb;
        va.x = acc[nt][0] + bv.x;  va.y = acc[nt][1] + bv.y;
        vb.x = acc[nt][2] + bv.x;  vb.y = acc[nt][3] + bv.y;
        if (do_silu) {
            va.x = va.x / (1.0f + __expf(-va.x));
            va.y = va.y / (1.0f + __expf(-va.y));
            vb.x = vb.x / (1.0f + __expf(-vb.x));
            vb.y = vb.y / (1.0f + __expf(-vb.y));
        }
        if (rowA < M) {
            *(float2*)(C1 + (size_t)rowA * H + col) = va;
            if (C2) *(float2*)(C2 + (size_t)rowA * H + col) = va;
        }
        if (rowB < M) {
            *(float2*)(C1 + (size_t)rowB * H + col) = vb;
            if (C2) *(float2*)(C2 + (size_t)rowB * H + col) = vb;
        }
    }
}

// ---------------------------------------------------------------------------
__global__ void batch_kernel(const int* __restrict__ b, float* __restrict__ o, int N)
{
    int i = blockIdx.x * blockDim.x + threadIdx.x;
    if (i < N) o[i] = (float)b[i];
}

// ---------------------------------------------------------------------------
extern "C" void kernel_launch(void* const* d_in, const int* in_sizes, int n_in,
                              void* d_out, int out_size)
{
    const float* emb = (const float*)d_in[0];
    const float* We  = (const float*)d_in[1];
    const float* be  = (const float*)d_in[2];
    const float* W1  = (const float*)d_in[3];
    const float* b1  = (const float*)d_in[4];
    const float* W2  = (const float*)d_in[5];
    const float* b2  = (const float*)d_in[6];
    const float* ea  = (const float*)d_in[7];
    const int*   z   = (const int*)d_in[8];
    const int*   ei  = (const int*)d_in[9];
    const int*   bat = (const int*)d_in[10];

    const int N = in_sizes[8];
    const int E = in_sizes[9] / 2;
    float* out = (float*)d_out;

    float *x, *agg, *u;
    cudaGetSymbolAddress((void**)&x, g_x);
    cudaGetSymbolAddress((void**)&agg, g_agg);
    cudaGetSymbolAddress((void**)&u, g_u);

    cudaFuncSetAttribute(gemm_tc_kernel, cudaFuncAttributeMaxDynamicSharedMemorySize, GEMM_SMEM);

    prep_weights_kernel<<<(6 * 128 * 32 + 255) / 256, 256>>>(W1, W2);
    embed_kernel<<<(N * (H / 4) + 255) / 256, 256>>>(emb, z, x, agg, N);

    const int tiles = (N + 127) / 128;

    for (int l = 0; l < 3; l++) {
        edge_kernel<<<1184, 256>>>(x, agg, ei, ei + E, ea,
                                   We + (size_t)l * 4 * H, be + (size_t)l * H, E);
        // u = silu(agg @ W1 + b1)
        gemm_tc_kernel<<<tiles, 256, GEMM_SMEM>>>(agg, l, b1 + (size_t)l * H, u, nullptr, N, 1);
        // x' = u @ W2 + b2  (dual-write x and agg for next layer)
        if (l == 2) {
            gemm_tc_kernel<<<tiles, 256, GEMM_SMEM>>>(u, 3 + l, b2 + (size_t)l * H, out, nullptr, N, 0);
        } else {
            gemm_tc_kernel<<<tiles, 256, GEMM_SMEM>>>(u, 3 + l, b2 + (size_t)l * H, x, agg, N, 0);
        }
    }

    if ((size_t)out_size >= (size_t)N * H + (size_t)N) {
        batch_kernel<<<(N + 255) / 256, 256>>>(bat, out + (size_t)N * H, N);
    }
}

// round 11
// speedup vs baseline: 1.0273x; 1.0273x over previous
#include <cuda_runtime.h>
#include <cuda_bf16.h>
#include <cstdint>

#define H 128
#define MAXN 100000
#define MAXE 600000
#define MAXNP (MAXN + 128)   // pad so unguarded tail-tile accesses stay in bounds

// ---------------------------------------------------------------------------
// Scratch (__device__ globals; no allocation allowed)
// ---------------------------------------------------------------------------
__device__ float g_x[MAXNP * H];                       // fp32 node features
// Packed activations: per row, 32 uint4 groups; group (kc,tig) at index kc*4+tig
// = {hi(k,k+1), hi(k+8,k+9), lo(k,k+1), lo(k+8,k+9)}, k = kc*16 + tig*2.
__device__ unsigned short g_aggp[MAXNP * H * 2];       // packed agg (gemm1 input)
__device__ unsigned short g_up[MAXNP * H * 2];         // packed u   (gemm2 input)
// Packed B fragments (weights), built once per call.
__device__ unsigned short g_Bpack[6 * 128 * 32 * 8];
// CSR
__device__ int g_rowptr[MAXN + 1];
__device__ int g_off[MAXN];
__device__ int g_bsum[128];
__device__ int g_eid[MAXE];

// ---------------------------------------------------------------------------
// Prep: build packed B fragment groups (one thread per 8-short group).
// ---------------------------------------------------------------------------
__global__ void prep_weights_kernel(const float* __restrict__ W1,
                                    const float* __restrict__ W2)
{
    int g = blockIdx.x * blockDim.x + threadIdx.x;
    if (g >= 6 * 128 * 32) return;
    int mat = g >> 12;
    int r = g & 4095;
    int nrow = r >> 5;
    int q = r & 31;
    int kc = q >> 2;
    int tig = q & 3;
    int k = kc * 16 + tig * 2;

    const float* W = (mat < 3) ? (W1 + (size_t)mat * H * H)
                               : (W2 + (size_t)(mat - 3) * H * H);
    unsigned short s[8];
    int kk[4] = {k, k + 1, k + 8, k + 9};
    #pragma unroll
    for (int j = 0; j < 4; j++) {
        float v = W[kk[j] * H + nrow];
        __nv_bfloat16 hi = __float2bfloat16(v);
        float res = v - __bfloat162float(hi);
        __nv_bfloat16 lo = __float2bfloat16(res);
        s[j] = __bfloat16_as_ushort(hi);
        s[4 + j] = __bfloat16_as_ushort(lo);
    }
    uint4 out;
    out.x = (uint32_t)s[0] | ((uint32_t)s[1] << 16);
    out.y = (uint32_t)s[2] | ((uint32_t)s[3] << 16);
    out.z = (uint32_t)s[4] | ((uint32_t)s[5] << 16);
    out.w = (uint32_t)s[6] | ((uint32_t)s[7] << 16);
    ((uint4*)g_Bpack)[g] = out;
}

// ---------------------------------------------------------------------------
// x[i] = emb[z[i]]
// ---------------------------------------------------------------------------
__global__ void embed_kernel(const float* __restrict__ emb,
                             const int* __restrict__ z,
                             float* __restrict__ x, int N)
{
    int i = blockIdx.x * blockDim.x + threadIdx.x;
    if (i >= N * (H / 4)) return;
    int row = i >> 5;
    int c = i & 31;
    ((float4*)x)[i] = ((const float4*)(emb + (size_t)z[row] * H))[c];
}

// ---------------------------------------------------------------------------
// CSR build (once per call; graph static across layers)
// ---------------------------------------------------------------------------
__global__ void csr_zero_kernel(int N)
{
    int i = blockIdx.x * blockDim.x + threadIdx.x;
    if (i < N) g_off[i] = 0;
}
__global__ void csr_hist_kernel(const int* __restrict__ dst, int E)
{
    int e = blockIdx.x * blockDim.x + threadIdx.x;
    if (e < E) atomicAdd(&g_off[dst[e]], 1);
}
// Per-block exclusive scan of g_off (chunk = 1024), partial sums to g_bsum.
__global__ void csr_scan1_kernel(int N)
{
    __shared__ int ts[256];
    int b = blockIdx.x, t = threadIdx.x;
    int base = b * 1024 + t * 4;
    int v0 = (base + 0 < N) ? g_off[base + 0] : 0;
    int v1 = (base + 1 < N) ? g_off[base + 1] : 0;
    int v2 = (base + 2 < N) ? g_off[base + 2] : 0;
    int v3 = (base + 3 < N) ? g_off[base + 3] : 0;
    int s = v0 + v1 + v2 + v3;
    ts[t] = s;
    __syncthreads();
    for (int d = 1; d < 256; d <<= 1) {
        int xv = (t >= d) ? ts[t - d] : 0;
        __syncthreads();
        ts[t] += xv;
        __syncthreads();
    }
    int run = ts[t] - s;                 // exclusive prefix of thread sums
    if (t == 255) g_bsum[b] = ts[255];
    if (base + 0 < N) g_rowptr[base + 0] = run;  run += v0;
    if (base + 1 < N) g_rowptr[base + 1] = run;  run += v1;
    if (base + 2 < N) g_rowptr[base + 2] = run;  run += v2;
    if (base + 3 < N) g_rowptr[base + 3] = run;
}
__global__ void csr_scan2_kernel(int nb, int N, int E)
{
    __shared__ int sv[128];
    int t = threadIdx.x;
    if (t < nb) sv[t] = g_bsum[t];
    __syncthreads();
    if (t == 0) {
        int run = 0;
        for (int i = 0; i < nb; i++) { int v = sv[i]; sv[i] = run; run += v; }
        g_rowptr[N] = E;
    }
    __syncthreads();
    if (t < nb) g_bsum[t] = sv[t];
}
__global__ void csr_scan3_kernel(int N)
{
    int i = blockIdx.x * blockDim.x + threadIdx.x;
    if (i < N) {
        int r = g_rowptr[i] + g_bsum[i >> 10];
        g_rowptr[i] = r;
        g_off[i] = r;
    }
}
__global__ void csr_scatter_kernel(const int* __restrict__ dst, int E)
{
    int e = blockIdx.x * blockDim.x + threadIdx.x;
    if (e < E) {
        int pos = atomicAdd(&g_off[dst[e]], 1);
        g_eid[pos] = e;
    }
}

// ---------------------------------------------------------------------------
// Aggregate (CSR, no atomics): one warp per node.
// Lane owns cols {k0, k0+1, k0+8, k0+9}, k0 = (lane/4)*16 + (lane%4)*2 — the
// exact pack-group mapping, so the final write is one uint4.
//   agg[n] = x[n] + sum_{e in in(n)} relu(x[src[e]] + ea[e] @ We + be)
// Output written directly as packed bf16 hi/lo fragments.
// ---------------------------------------------------------------------------
__global__ __launch_bounds__(256) void agg_pack_kernel(
    const float* __restrict__ x,
    const int* __restrict__ src,
    const float* __restrict__ ea,
    const float* __restrict__ We,
    const float* __restrict__ be,
    unsigned short* __restrict__ Apack,
    int N)
{
    int warp = (blockIdx.x * blockDim.x + threadIdx.x) >> 5;
    if (warp >= N) return;
    const int n = warp;
    const int lane = threadIdx.x & 31;
    const int k0 = ((lane >> 2) << 4) + ((lane & 3) << 1);

    const float2 w0a = *(const float2*)(We + 0 * H + k0);
    const float2 w0b = *(const float2*)(We + 0 * H + k0 + 8);
    const float2 w1a = *(const float2*)(We + 1 * H + k0);
    const float2 w1b = *(const float2*)(We + 1 * H + k0 + 8);
    const float2 w2a = *(const float2*)(We + 2 * H + k0);
    const float2 w2b = *(const float2*)(We + 2 * H + k0 + 8);
    const float2 w3a = *(const float2*)(We + 3 * H + k0);
    const float2 w3b = *(const float2*)(We + 3 * H + k0 + 8);
    const float2 bea = *(const float2*)(be + k0);
    const float2 beb = *(const float2*)(be + k0 + 8);

    float2 sa = *(const float2*)(x + (size_t)n * H + k0);
    float2 sb = *(const float2*)(x + (size_t)n * H + k0 + 8);

    const int beg = g_rowptr[n], end = g_rowptr[n + 1];
    for (int i = beg; i < end; i++) {
        int e = g_eid[i];
        int s = __ldg(src + e);
        float4 av = *(const float4*)(ea + 4 * (size_t)e);

        float2 pa, pb;
        pa.x = bea.x + av.x * w0a.x + av.y * w1a.x + av.z * w2a.x + av.w * w3a.x;
        pa.y = bea.y + av.x * w0a.y + av.y * w1a.y + av.z * w2a.y + av.w * w3a.y;
        pb.x = beb.x + av.x * w0b.x + av.y * w1b.x + av.z * w2b.x + av.w * w3b.x;
        pb.y = beb.y + av.x * w0b.y + av.y * w1b.y + av.z * w2b.y + av.w * w3b.y;

        float2 xa = *(const float2*)(x + (size_t)s * H + k0);
        float2 xb = *(const float2*)(x + (size_t)s * H + k0 + 8);
        sa.x += fmaxf(xa.x + pa.x, 0.0f);
        sa.y += fmaxf(xa.y + pa.y, 0.0f);
        sb.x += fmaxf(xb.x + pb.x, 0.0f);
        sb.y += fmaxf(xb.y + pb.y, 0.0f);
    }

    __nv_bfloat162 ha = __floats2bfloat162_rn(sa.x, sa.y);
    __nv_bfloat162 hb = __floats2bfloat162_rn(sb.x, sb.y);
    __nv_bfloat162 la = __floats2bfloat162_rn(sa.x - __low2float(ha), sa.y - __high2float(ha));
    __nv_bfloat162 lb = __floats2bfloat162_rn(sb.x - __low2float(hb), sb.y - __high2float(hb));
    uint4 pk;
    pk.x = *(uint32_t*)&ha; pk.y = *(uint32_t*)&hb;
    pk.z = *(uint32_t*)&la; pk.w = *(uint32_t*)&lb;
    ((uint4*)Apack)[(size_t)n * 32 + lane] = pk;
}

// ---------------------------------------------------------------------------
// Tensor-core GEMM, split-bf16 fp32 emulation, pre-packed A:
//   C[M,128] = act(A[M,128] @ W[128,128] + bias), D = Ahi*Bhi + Ahi*Blo + Alo*Bhi.
// CTA: 256 thr / 8 warps, 128-row tile. B staged packed in smem (576B row
// stride, conflict-free LDS.128). A read as 2 x LDG.128 per kc, depth-2
// prefetch, zero conversion math. Output: packed (Cp) or fp32 (Cf).
// ---------------------------------------------------------------------------
#define BROW 576
#define GEMM_SMEM (128 * BROW)                    // 73728 B -> 2 CTAs/SM

__device__ __forceinline__ void mma_bf16(float* c, const uint32_t* a,
                                         uint32_t b0, uint32_t b1)
{
    asm volatile(
        "mma.sync.aligned.m16n8k16.row.col.f32.bf16.bf16.f32 "
        "{%0,%1,%2,%3}, {%4,%5,%6,%7}, {%8,%9}, {%0,%1,%2,%3};"
        : "+f"(c[0]), "+f"(c[1]), "+f"(c[2]), "+f"(c[3])
        : "r"(a[0]), "r"(a[1]), "r"(a[2]), "r"(a[3]), "r"(b0), "r"(b1));
}

__device__ __forceinline__ float silu(float v) { return v / (1.0f + __expf(-v)); }

__global__ __launch_bounds__(256, 2) void gemm_tc_kernel(
    const unsigned short* __restrict__ Apack, int mat,
    const float* __restrict__ bias,
    float* __restrict__ Cf, unsigned short* __restrict__ Cp,
    int M, int do_silu)
{
    extern __shared__ char smraw[];

    const int tid = threadIdx.x;
    const int wid = tid >> 5;
    const int lane = tid & 31;
    const int gid = lane >> 2;
    const int tig = lane & 3;
    const int row0 = blockIdx.x * 128;
    const int rbase = wid * 16;

    // ---- Stage packed B: 4096 uint4 (64 KB), row padded 512->576 B ----
    {
        const uint4* gp = (const uint4*)g_Bpack + (size_t)mat * 4096;
        #pragma unroll
        for (int it = 0; it < 16; it++) {
            int i = tid + it * 256;
            int row = i >> 5;
            int g = i & 31;
            *(uint4*)(smraw + row * BROW + g * 16) = gp[i];
        }
    }

    // A fragment pointers (packed rows; pad rows make unguarded loads safe)
    const uint4* Ap0 = (const uint4*)Apack + (size_t)(row0 + rbase + gid) * 32 + tig;
    const uint4* Ap1 = Ap0 + 8 * 32;

    float acc[16][4];
    #pragma unroll
    for (int nt = 0; nt < 16; nt++)
        acc[nt][0] = acc[nt][1] = acc[nt][2] = acc[nt][3] = 0.0f;

    // Depth-2 prefetch
    uint4 c0a = Ap0[0], c0b = Ap1[0];
    uint4 c1a = Ap0[4], c1b = Ap1[4];

    __syncthreads();   // B ready

    #pragma unroll
    for (int kc = 0; kc < 8; kc++) {
        uint4 fa = c0a, fb = c0b;
        c0a = c1a; c0b = c1b;
        if (kc < 6) {
            c1a = Ap0[(kc + 2) * 4];
            c1b = Ap1[(kc + 2) * 4];
        }
        uint32_t ahi[4] = {fa.x, fb.x, fa.y, fb.y};
        uint32_t alo[4] = {fa.z, fb.z, fa.w, fb.w};

        const int koff = (kc * 4 + tig) * 16;
        #pragma unroll
        for (int nt = 0; nt < 16; nt++) {
            const int nrow = nt * 8 + gid;
            uint4 b = *(const uint4*)(smraw + nrow * BROW + koff);
            mma_bf16(acc[nt], ahi, b.x, b.y);   // Ahi * Bhi
            mma_bf16(acc[nt], ahi, b.z, b.w);   // Ahi * Blo
            mma_bf16(acc[nt], alo, b.x, b.y);   // Alo * Bhi
        }
    }

    // ---- Epilogue ----
    const int rowA = row0 + rbase + gid;
    const int rowB = rowA + 8;
    #pragma unroll
    for (int kc = 0; kc < 8; kc++) {
        const int colA = kc * 16 + tig * 2;      // nt = 2kc
        const int colB = colA + 8;               // nt = 2kc+1
        float2 bva = __ldg((const float2*)(bias + colA));
        float2 bvb = __ldg((const float2*)(bias + colB));
        float va0x = acc[2*kc][0] + bva.x,   va0y = acc[2*kc][1] + bva.y;
        float va1x = acc[2*kc+1][0] + bvb.x, va1y = acc[2*kc+1][1] + bvb.y;
        float vb0x = acc[2*kc][2] + bva.x,   vb0y = acc[2*kc][3] + bva.y;
        float vb1x = acc[2*kc+1][2] + bvb.x, vb1y = acc[2*kc+1][3] + bvb.y;
        if (do_silu) {
            va0x = silu(va0x); va0y = silu(va0y); va1x = silu(va1x); va1y = silu(va1y);
            vb0x = silu(vb0x); vb0y = silu(vb0y); vb1x = silu(vb1x); vb1y = silu(vb1y);
        }
        if (Cp) {
            // packed store (buffers padded; unguarded rows harmless)
            __nv_bfloat162 ha = __floats2bfloat162_rn(va0x, va0y);
            __nv_bfloat162 hb = __floats2bfloat162_rn(va1x, va1y);
            __nv_bfloat162 la = __floats2bfloat162_rn(va0x - __low2float(ha), va0y - __high2float(ha));
            __nv_bfloat162 lb = __floats2bfloat162_rn(va1x - __low2float(hb), va1y - __high2float(hb));
            uint4 pk;
            pk.x = *(uint32_t*)&ha; pk.y = *(uint32_t*)&hb;
            pk.z = *(uint32_t*)&la; pk.w = *(uint32_t*)&lb;
            ((uint4*)Cp)[(size_t)rowA * 32 + kc * 4 + tig] = pk;

            ha = __floats2bfloat162_rn(vb0x, vb0y);
            hb = __floats2bfloat162_rn(vb1x, vb1y);
            la = __floats2bfloat162_rn(vb0x - __low2float(ha), vb0y - __high2float(ha));
            lb = __floats2bfloat162_rn(vb1x - __low2float(hb), vb1y - __high2float(hb));
            pk.x = *(uint32_t*)&ha; pk.y = *(uint32_t*)&hb;
            pk.z = *(uint32_t*)&la; pk.w = *(uint32_t*)&lb;
            ((uint4*)Cp)[(size_t)rowB * 32 + kc * 4 + tig] = pk;
        } else {
            if (rowA < M) {
                *(float2*)(Cf + (size_t)rowA * H + colA) = make_float2(va0x, va0y);
                *(float2*)(Cf + (size_t)rowA * H + colB) = make_float2(va1x, va1y);
            }
            if (rowB < M) {
                *(float2*)(Cf + (size_t)rowB * H + colA) = make_float2(vb0x, vb0y);
                *(float2*)(Cf + (size_t)rowB * H + colB) = make_float2(vb1x, vb1y);
            }
        }
    }
}

// ---------------------------------------------------------------------------
__global__ void batch_kernel(const int* __restrict__ b, float* __restrict__ o, int N)
{
    int i = blockIdx.x * blockDim.x + threadIdx.x;
    if (i < N) o[i] = (float)b[i];
}

// ---------------------------------------------------------------------------
extern "C" void kernel_launch(void* const* d_in, const int* in_sizes, int n_in,
                              void* d_out, int out_size)
{
    const float* emb = (const float*)d_in[0];
    const float* We  = (const float*)d_in[1];
    const float* be  = (const float*)d_in[2];
    const float* W1  = (const float*)d_in[3];
    const float* b1  = (const float*)d_in[4];
    const float* W2  = (const float*)d_in[5];
    const float* b2  = (const float*)d_in[6];
    const float* ea  = (const float*)d_in[7];
    const int*   z   = (const int*)d_in[8];
    const int*   ei  = (const int*)d_in[9];
    const int*   bat = (const int*)d_in[10];

    const int N = in_sizes[8];
    const int E = in_sizes[9] / 2;
    float* out = (float*)d_out;

    float* x;
    unsigned short *aggp, *up;
    cudaGetSymbolAddress((void**)&x, g_x);
    cudaGetSymbolAddress((void**)&aggp, g_aggp);
    cudaGetSymbolAddress((void**)&up, g_up);

    cudaFuncSetAttribute(gemm_tc_kernel, cudaFuncAttributeMaxDynamicSharedMemorySize, GEMM_SMEM);

    prep_weights_kernel<<<(6 * 128 * 32 + 255) / 256, 256>>>(W1, W2);
    embed_kernel<<<(N * (H / 4) + 255) / 256, 256>>>(emb, z, x, N);

    // CSR build (once; graph static across layers)
    const int* srcp = ei;
    const int* dstp = ei + E;
    const int nb = (N + 1023) / 1024;
    csr_zero_kernel<<<(N + 255) / 256, 256>>>(N);
    csr_hist_kernel<<<(E + 255) / 256, 256>>>(dstp, E);
    csr_scan1_kernel<<<nb, 256>>>(N);
    csr_scan2_kernel<<<1, 128>>>(nb, N, E);
    csr_scan3_kernel<<<(N + 255) / 256, 256>>>(N);
    csr_scatter_kernel<<<(E + 255) / 256, 256>>>(dstp, E);

    const int tiles = (N + 127) / 128;
    const int agg_grid = (N * 32 + 255) / 256;

    for (int l = 0; l < 3; l++) {
        agg_pack_kernel<<<agg_grid, 256>>>(x, srcp, ea,
                                           We + (size_t)l * 4 * H, be + (size_t)l * H,
                                           aggp, N);
        // u = silu(agg @ W1 + b1) -> packed
        gemm_tc_kernel<<<tiles, 256, GEMM_SMEM>>>(aggp, l, b1 + (size_t)l * H,
                                                  nullptr, up, N, 1);
        // x' = u @ W2 + b2 -> fp32 (or final output)
        gemm_tc_kernel<<<tiles, 256, GEMM_SMEM>>>(up, 3 + l, b2 + (size_t)l * H,
                                                  (l == 2) ? out : x, nullptr, N, 0);
    }

    if ((size_t)out_size >= (size_t)N * H + (size_t)N) {
        batch_kernel<<<(N + 255) / 256, 256>>>(bat, out + (size_t)N * H, N);
    }
}

// round 12
// speedup vs baseline: 1.0655x; 1.0372x over previous
#include <cuda_runtime.h>
#include <cuda_bf16.h>
#include <cstdint>

#define H 128
#define MAXN 100000
#define MAXE 600000
#define MAXNP (MAXN + 128)   // pad so unguarded tail-tile accesses stay in bounds

// ---------------------------------------------------------------------------
// Scratch (__device__ globals; no allocation allowed)
// ---------------------------------------------------------------------------
__device__ float g_x[MAXNP * H];                       // fp32 node features
// Packed activations: per row, 32 uint4 groups; group (kc,tig) at index kc*4+tig
// = {hi(k,k+1), hi(k+8,k+9), lo(k,k+1), lo(k+8,k+9)}, k = kc*16 + tig*2.
__device__ unsigned short g_aggp[MAXNP * H * 2];       // packed agg (MLP input)
// Packed B fragments (weights), built once per call.
__device__ unsigned short g_Bpack[6 * 128 * 32 * 8];
// CSR
__device__ int g_rowptr[MAXN + 1];
__device__ int g_off[MAXN];
__device__ int g_bsum[128];
__device__ int g_eid[MAXE];

// ---------------------------------------------------------------------------
// Prep: build packed B fragment groups (one thread per 8-short group).
// ---------------------------------------------------------------------------
__global__ void prep_weights_kernel(const float* __restrict__ W1,
                                    const float* __restrict__ W2)
{
    int g = blockIdx.x * blockDim.x + threadIdx.x;
    if (g >= 6 * 128 * 32) return;
    int mat = g >> 12;
    int r = g & 4095;
    int nrow = r >> 5;
    int q = r & 31;
    int kc = q >> 2;
    int tig = q & 3;
    int k = kc * 16 + tig * 2;

    const float* W = (mat < 3) ? (W1 + (size_t)mat * H * H)
                               : (W2 + (size_t)(mat - 3) * H * H);
    unsigned short s[8];
    int kk[4] = {k, k + 1, k + 8, k + 9};
    #pragma unroll
    for (int j = 0; j < 4; j++) {
        float v = W[kk[j] * H + nrow];
        __nv_bfloat16 hi = __float2bfloat16(v);
        float res = v - __bfloat162float(hi);
        __nv_bfloat16 lo = __float2bfloat16(res);
        s[j] = __bfloat16_as_ushort(hi);
        s[4 + j] = __bfloat16_as_ushort(lo);
    }
    uint4 out;
    out.x = (uint32_t)s[0] | ((uint32_t)s[1] << 16);
    out.y = (uint32_t)s[2] | ((uint32_t)s[3] << 16);
    out.z = (uint32_t)s[4] | ((uint32_t)s[5] << 16);
    out.w = (uint32_t)s[6] | ((uint32_t)s[7] << 16);
    ((uint4*)g_Bpack)[g] = out;
}

// ---------------------------------------------------------------------------
// x[i] = emb[z[i]]
// ---------------------------------------------------------------------------
__global__ void embed_kernel(const float* __restrict__ emb,
                             const int* __restrict__ z,
                             float* __restrict__ x, int N)
{
    int i = blockIdx.x * blockDim.x + threadIdx.x;
    if (i >= N * (H / 4)) return;
    int row = i >> 5;
    int c = i & 31;
    ((float4*)x)[i] = ((const float4*)(emb + (size_t)z[row] * H))[c];
}

// ---------------------------------------------------------------------------
// CSR build (once per call; graph static across layers)
// ---------------------------------------------------------------------------
__global__ void csr_zero_kernel(int N)
{
    int i = blockIdx.x * blockDim.x + threadIdx.x;
    if (i < N) g_off[i] = 0;
}
__global__ void csr_hist_kernel(const int* __restrict__ dst, int E)
{
    int e = blockIdx.x * blockDim.x + threadIdx.x;
    if (e < E) atomicAdd(&g_off[dst[e]], 1);
}
__global__ void csr_scan1_kernel(int N)
{
    __shared__ int ts[256];
    int b = blockIdx.x, t = threadIdx.x;
    int base = b * 1024 + t * 4;
    int v0 = (base + 0 < N) ? g_off[base + 0] : 0;
    int v1 = (base + 1 < N) ? g_off[base + 1] : 0;
    int v2 = (base + 2 < N) ? g_off[base + 2] : 0;
    int v3 = (base + 3 < N) ? g_off[base + 3] : 0;
    int s = v0 + v1 + v2 + v3;
    ts[t] = s;
    __syncthreads();
    for (int d = 1; d < 256; d <<= 1) {
        int xv = (t >= d) ? ts[t - d] : 0;
        __syncthreads();
        ts[t] += xv;
        __syncthreads();
    }
    int run = ts[t] - s;
    if (t == 255) g_bsum[b] = ts[255];
    if (base + 0 < N) g_rowptr[base + 0] = run;  run += v0;
    if (base + 1 < N) g_rowptr[base + 1] = run;  run += v1;
    if (base + 2 < N) g_rowptr[base + 2] = run;  run += v2;
    if (base + 3 < N) g_rowptr[base + 3] = run;
}
__global__ void csr_scan2_kernel(int nb, int N, int E)
{
    __shared__ int sv[128];
    int t = threadIdx.x;
    if (t < nb) sv[t] = g_bsum[t];
    __syncthreads();
    if (t == 0) {
        int run = 0;
        for (int i = 0; i < nb; i++) { int v = sv[i]; sv[i] = run; run += v; }
        g_rowptr[N] = E;
    }
    __syncthreads();
    if (t < nb) g_bsum[t] = sv[t];
}
__global__ void csr_scan3_kernel(int N)
{
    int i = blockIdx.x * blockDim.x + threadIdx.x;
    if (i < N) {
        int r = g_rowptr[i] + g_bsum[i >> 10];
        g_rowptr[i] = r;
        g_off[i] = r;
    }
}
__global__ void csr_scatter_kernel(const int* __restrict__ dst, int E)
{
    int e = blockIdx.x * blockDim.x + threadIdx.x;
    if (e < E) {
        int pos = atomicAdd(&g_off[dst[e]], 1);
        g_eid[pos] = e;
    }
}

// ---------------------------------------------------------------------------
// Aggregate (CSR, no atomics): one warp per node; output packed bf16 hi/lo.
// ---------------------------------------------------------------------------
__global__ __launch_bounds__(256) void agg_pack_kernel(
    const float* __restrict__ x,
    const int* __restrict__ src,
    const float* __restrict__ ea,
    const float* __restrict__ We,
    const float* __restrict__ be,
    unsigned short* __restrict__ Apack,
    int N)
{
    int warp = (blockIdx.x * blockDim.x + threadIdx.x) >> 5;
    if (warp >= N) return;
    const int n = warp;
    const int lane = threadIdx.x & 31;
    const int k0 = ((lane >> 2) << 4) + ((lane & 3) << 1);

    const float2 w0a = *(const float2*)(We + 0 * H + k0);
    const float2 w0b = *(const float2*)(We + 0 * H + k0 + 8);
    const float2 w1a = *(const float2*)(We + 1 * H + k0);
    const float2 w1b = *(const float2*)(We + 1 * H + k0 + 8);
    const float2 w2a = *(const float2*)(We + 2 * H + k0);
    const float2 w2b = *(const float2*)(We + 2 * H + k0 + 8);
    const float2 w3a = *(const float2*)(We + 3 * H + k0);
    const float2 w3b = *(const float2*)(We + 3 * H + k0 + 8);
    const float2 bea = *(const float2*)(be + k0);
    const float2 beb = *(const float2*)(be + k0 + 8);

    float2 sa = *(const float2*)(x + (size_t)n * H + k0);
    float2 sb = *(const float2*)(x + (size_t)n * H + k0 + 8);

    const int beg = g_rowptr[n], end = g_rowptr[n + 1];
    for (int i = beg; i < end; i++) {
        int e = g_eid[i];
        int s = __ldg(src + e);
        float4 av = *(const float4*)(ea + 4 * (size_t)e);

        float2 pa, pb;
        pa.x = bea.x + av.x * w0a.x + av.y * w1a.x + av.z * w2a.x + av.w * w3a.x;
        pa.y = bea.y + av.x * w0a.y + av.y * w1a.y + av.z * w2a.y + av.w * w3a.y;
        pb.x = beb.x + av.x * w0b.x + av.y * w1b.x + av.z * w2b.x + av.w * w3b.x;
        pb.y = beb.y + av.x * w0b.y + av.y * w1b.y + av.z * w2b.y + av.w * w3b.y;

        float2 xa = *(const float2*)(x + (size_t)s * H + k0);
        float2 xb = *(const float2*)(x + (size_t)s * H + k0 + 8);
        sa.x += fmaxf(xa.x + pa.x, 0.0f);
        sa.y += fmaxf(xa.y + pa.y, 0.0f);
        sb.x += fmaxf(xb.x + pb.x, 0.0f);
        sb.y += fmaxf(xb.y + pb.y, 0.0f);
    }

    __nv_bfloat162 ha = __floats2bfloat162_rn(sa.x, sa.y);
    __nv_bfloat162 hb = __floats2bfloat162_rn(sb.x, sb.y);
    __nv_bfloat162 la = __floats2bfloat162_rn(sa.x - __low2float(ha), sa.y - __high2float(ha));
    __nv_bfloat162 lb = __floats2bfloat162_rn(sb.x - __low2float(hb), sb.y - __high2float(hb));
    uint4 pk;
    pk.x = *(uint32_t*)&ha; pk.y = *(uint32_t*)&hb;
    pk.z = *(uint32_t*)&la; pk.w = *(uint32_t*)&lb;
    ((uint4*)Apack)[(size_t)n * 32 + lane] = pk;
}

// ---------------------------------------------------------------------------
// Fused MLP (both GEMMs, one kernel), split-bf16 fp32 emulation:
//   X' = (silu(A @ W1 + b1)) @ W2 + b2
// Register identity: warp w's gemm1 C-fragments for tiles nt=2kc,2kc+1 ARE the
// gemm2 A-fragment for k-chunk kc (rows w*16..+15). U never touches gmem:
// hi-fragments via a 32KB smem region, lo-fragments stay in registers.
// Smem: B region 73.7KB (staged B1, then re-staged B2) + U region 32KB.
// ---------------------------------------------------------------------------
#define BROW 576
#define U_OFF (128 * BROW)                         // 73728
#define MLP_SMEM (U_OFF + 32768)                   // 106496 B -> 2 CTAs/SM

__device__ __forceinline__ void mma_bf16(float* c, const uint32_t* a,
                                         uint32_t b0, uint32_t b1)
{
    asm volatile(
        "mma.sync.aligned.m16n8k16.row.col.f32.bf16.bf16.f32 "
        "{%0,%1,%2,%3}, {%4,%5,%6,%7}, {%8,%9}, {%0,%1,%2,%3};"
        : "+f"(c[0]), "+f"(c[1]), "+f"(c[2]), "+f"(c[3])
        : "r"(a[0]), "r"(a[1]), "r"(a[2]), "r"(a[3]), "r"(b0), "r"(b1));
}

__device__ __forceinline__ float silu(float v) { return v / (1.0f + __expf(-v)); }

__device__ __forceinline__ void stage_B(char* smraw, int mat, int tid)
{
    const uint4* gp = (const uint4*)g_Bpack + (size_t)mat * 4096;
    #pragma unroll
    for (int it = 0; it < 16; it++) {
        int i = tid + it * 256;
        int row = i >> 5;
        int g = i & 31;
        *(uint4*)(smraw + row * BROW + g * 16) = gp[i];
    }
}

__global__ __launch_bounds__(256, 2) void mlp_fused_kernel(
    const unsigned short* __restrict__ Apack,
    int mat1, const float* __restrict__ bias1,
    int mat2, const float* __restrict__ bias2,
    float* __restrict__ Cf, int M)
{
    extern __shared__ char smraw[];

    const int tid = threadIdx.x;
    const int wid = tid >> 5;
    const int lane = tid & 31;
    const int gid = lane >> 2;
    const int tig = lane & 3;
    const int row0 = blockIdx.x * 128;
    const int rbase = wid * 16;

    // U region: per (warp, kc) a 512B slab, lane*16 within. Conflict-free LDS.128.
    char* Ubase = smraw + U_OFF + (wid * 8) * 512 + lane * 16;

    stage_B(smraw, mat1, tid);

    const uint4* Ap0 = (const uint4*)Apack + (size_t)(row0 + rbase + gid) * 32 + tig;
    const uint4* Ap1 = Ap0 + 8 * 32;

    float acc[16][4];
    #pragma unroll
    for (int nt = 0; nt < 16; nt++)
        acc[nt][0] = acc[nt][1] = acc[nt][2] = acc[nt][3] = 0.0f;

    uint4 c0a = Ap0[0], c0b = Ap1[0];
    uint4 c1a = Ap0[4], c1b = Ap1[4];

    __syncthreads();   // B1 ready

    // ---- Phase 1: U = A @ W1 ----
    #pragma unroll
    for (int kc = 0; kc < 8; kc++) {
        uint4 fa = c0a, fb = c0b;
        c0a = c1a; c0b = c1b;
        if (kc < 6) {
            c1a = Ap0[(kc + 2) * 4];
            c1b = Ap1[(kc + 2) * 4];
        }
        uint32_t ahi[4] = {fa.x, fb.x, fa.y, fb.y};
        uint32_t alo[4] = {fa.z, fb.z, fa.w, fb.w};

        const int koff = (kc * 4 + tig) * 16;
        #pragma unroll
        for (int nt = 0; nt < 16; nt++) {
            const int nrow = nt * 8 + gid;
            uint4 b = *(const uint4*)(smraw + nrow * BROW + koff);
            mma_bf16(acc[nt], ahi, b.x, b.y);
            mma_bf16(acc[nt], ahi, b.z, b.w);
            mma_bf16(acc[nt], alo, b.x, b.y);
        }
    }

    // ---- Convert: bias1 + silu + bf16 split. hi -> smem U, lo -> regs ----
    uint32_t ulo[8][4];
    #pragma unroll
    for (int kc = 0; kc < 8; kc++) {
        const int colA = kc * 16 + tig * 2;
        float2 bva = __ldg((const float2*)(bias1 + colA));
        float2 bvb = __ldg((const float2*)(bias1 + colA + 8));
        // a0 = (row gid, k0,k0+1), a1 = (row gid+8, k0,k0+1),
        // a2 = (row gid, k0+8,+9), a3 = (row gid+8, k0+8,+9)
        float v0x = silu(acc[2*kc][0] + bva.x),   v0y = silu(acc[2*kc][1] + bva.y);
        float v1x = silu(acc[2*kc][2] + bva.x),   v1y = silu(acc[2*kc][3] + bva.y);
        float v2x = silu(acc[2*kc+1][0] + bvb.x), v2y = silu(acc[2*kc+1][1] + bvb.y);
        float v3x = silu(acc[2*kc+1][2] + bvb.x), v3y = silu(acc[2*kc+1][3] + bvb.y);

        __nv_bfloat162 h0 = __floats2bfloat162_rn(v0x, v0y);
        __nv_bfloat162 h1 = __floats2bfloat162_rn(v1x, v1y);
        __nv_bfloat162 h2 = __floats2bfloat162_rn(v2x, v2y);
        __nv_bfloat162 h3 = __floats2bfloat162_rn(v3x, v3y);
        __nv_bfloat162 l0 = __floats2bfloat162_rn(v0x - __low2float(h0), v0y - __high2float(h0));
        __nv_bfloat162 l1 = __floats2bfloat162_rn(v1x - __low2float(h1), v1y - __high2float(h1));
        __nv_bfloat162 l2 = __floats2bfloat162_rn(v2x - __low2float(h2), v2y - __high2float(h2));
        __nv_bfloat162 l3 = __floats2bfloat162_rn(v3x - __low2float(h3), v3y - __high2float(h3));

        uint4 uh;
        uh.x = *(uint32_t*)&h0; uh.y = *(uint32_t*)&h1;
        uh.z = *(uint32_t*)&h2; uh.w = *(uint32_t*)&h3;
        *(uint4*)(Ubase + kc * 512) = uh;
        ulo[kc][0] = *(uint32_t*)&l0; ulo[kc][1] = *(uint32_t*)&l1;
        ulo[kc][2] = *(uint32_t*)&l2; ulo[kc][3] = *(uint32_t*)&l3;
    }

    __syncthreads();   // all B1 reads done; U hi written

    stage_B(smraw, mat2, tid);

    #pragma unroll
    for (int nt = 0; nt < 16; nt++)
        acc[nt][0] = acc[nt][1] = acc[nt][2] = acc[nt][3] = 0.0f;

    __syncthreads();   // B2 ready

    // ---- Phase 2: X' = U @ W2 (A-hi from smem, A-lo from regs) ----
    #pragma unroll
    for (int kc = 0; kc < 8; kc++) {
        uint4 uh = *(const uint4*)(Ubase + kc * 512);
        uint32_t ahi[4] = {uh.x, uh.y, uh.z, uh.w};

        const int koff = (kc * 4 + tig) * 16;
        #pragma unroll
        for (int nt = 0; nt < 16; nt++) {
            const int nrow = nt * 8 + gid;
            uint4 b = *(const uint4*)(smraw + nrow * BROW + koff);
            mma_bf16(acc[nt], ahi, b.x, b.y);
            mma_bf16(acc[nt], ahi, b.z, b.w);
            mma_bf16(acc[nt], ulo[kc], b.x, b.y);
        }
    }

    // ---- Epilogue: bias2 + fp32 store ----
    const int rowA = row0 + rbase + gid;
    const int rowB = rowA + 8;
    #pragma unroll
    for (int kc = 0; kc < 8; kc++) {
        const int colA = kc * 16 + tig * 2;
        const int colB = colA + 8;
        float2 bva = __ldg((const float2*)(bias2 + colA));
        float2 bvb = __ldg((const float2*)(bias2 + colB));
        if (rowA < M) {
            *(float2*)(Cf + (size_t)rowA * H + colA) =
                make_float2(acc[2*kc][0] + bva.x, acc[2*kc][1] + bva.y);
            *(float2*)(Cf + (size_t)rowA * H + colB) =
                make_float2(acc[2*kc+1][0] + bvb.x, acc[2*kc+1][1] + bvb.y);
        }
        if (rowB < M) {
            *(float2*)(Cf + (size_t)rowB * H + colA) =
                make_float2(acc[2*kc][2] + bva.x, acc[2*kc][3] + bva.y);
            *(float2*)(Cf + (size_t)rowB * H + colB) =
                make_float2(acc[2*kc+1][2] + bvb.x, acc[2*kc+1][3] + bvb.y);
        }
    }
}

// ---------------------------------------------------------------------------
__global__ void batch_kernel(const int* __restrict__ b, float* __restrict__ o, int N)
{
    int i = blockIdx.x * blockDim.x + threadIdx.x;
    if (i < N) o[i] = (float)b[i];
}

// ---------------------------------------------------------------------------
extern "C" void kernel_launch(void* const* d_in, const int* in_sizes, int n_in,
                              void* d_out, int out_size)
{
    const float* emb = (const float*)d_in[0];
    const float* We  = (const float*)d_in[1];
    const float* be  = (const float*)d_in[2];
    const float* W1  = (const float*)d_in[3];
    const float* b1  = (const float*)d_in[4];
    const float* W2  = (const float*)d_in[5];
    const float* b2  = (const float*)d_in[6];
    const float* ea  = (const float*)d_in[7];
    const int*   z   = (const int*)d_in[8];
    const int*   ei  = (const int*)d_in[9];
    const int*   bat = (const int*)d_in[10];

    const int N = in_sizes[8];
    const int E = in_sizes[9] / 2;
    float* out = (float*)d_out;

    float* x;
    unsigned short* aggp;
    cudaGetSymbolAddress((void**)&x, g_x);
    cudaGetSymbolAddress((void**)&aggp, g_aggp);

    cudaFuncSetAttribute(mlp_fused_kernel, cudaFuncAttributeMaxDynamicSharedMemorySize, MLP_SMEM);

    prep_weights_kernel<<<(6 * 128 * 32 + 255) / 256, 256>>>(W1, W2);
    embed_kernel<<<(N * (H / 4) + 255) / 256, 256>>>(emb, z, x, N);

    // CSR build (once; graph static across layers)
    const int* srcp = ei;
    const int* dstp = ei + E;
    const int nb = (N + 1023) / 1024;
    csr_zero_kernel<<<(N + 255) / 256, 256>>>(N);
    csr_hist_kernel<<<(E + 255) / 256, 256>>>(dstp, E);
    csr_scan1_kernel<<<nb, 256>>>(N);
    csr_scan2_kernel<<<1, 128>>>(nb, N, E);
    csr_scan3_kernel<<<(N + 255) / 256, 256>>>(N);
    csr_scatter_kernel<<<(E + 255) / 256, 256>>>(dstp, E);

    const int tiles = (N + 127) / 128;
    const int agg_grid = (N * 32 + 255) / 256;

    for (int l = 0; l < 3; l++) {
        agg_pack_kernel<<<agg_grid, 256>>>(x, srcp, ea,
                                           We + (size_t)l * 4 * H, be + (size_t)l * H,
                                           aggp, N);
        mlp_fused_kernel<<<tiles, 256, MLP_SMEM>>>(
            aggp,
            l, b1 + (size_t)l * H,
            3 + l, b2 + (size_t)l * H,
            (l == 2) ? out : x, N);
    }

    if ((size_t)out_size >= (size_t)N * H + (size_t)N) {
        batch_kernel<<<(N + 255) / 256, 256>>>(bat, out + (size_t)N * H, N);
    }
}